// round 10
// baseline (speedup 1.0000x reference)
#include <cuda_runtime.h>
#include <math.h>

// Problem constants
#define TOKS   4096   // B*N
#define DDIM   512
#define SSLOTS 1024
#define QDIM   320
#define KSEL   32
#define NHEAD  8
#define DHEAD  64

typedef unsigned long long u64t;
typedef unsigned int u32t;

// ---------------- scratch (device globals; no allocation allowed) ----------
__device__ float g_keysN[SSLOTS * DDIM];
__device__ float g_valsN[SSLOTS * DDIM];
__device__ float g_Kp[SSLOTS * DDIM];
__device__ float g_Vp[SSLOTS * DDIM];
__device__ float g_qh[TOKS * DDIM];
__device__ float g_scores[TOKS * SSLOTS];
__device__ float g_ctx[TOKS * DDIM];
__device__ float g_ctxo[TOKS * DDIM];
__device__ float g_normed[TOKS * DDIM];
__device__ float g_WqpT[QDIM * DDIM];   // Wqp transposed [320,512]
__device__ float g_Wqq[DDIM * QDIM];    // Wq @ Wqp       [512,320]
__device__ float g_M[SSLOTS * QDIM];    // keysN @ Wqp    [1024,320]

struct GT {
    const float* A;
    const float* B;
    float*       C;
    int N, K;
    const float* bias;
    int tilesX;   // N / tile_n
    int prec3;    // 1 = 3xTF32 split-precision (fp32-class accuracy)
};

#define TBK 16
#define SSTR 20   // smem row stride (words)

__device__ __forceinline__ u32t cvt_tf32(float x) {
    u32t r;
    asm("cvt.rna.tf32.f32 %0, %1;" : "=r"(r) : "f"(x));
    return r;
}
__device__ __forceinline__ u32t smem_u32(const void* p) {
    return (u32t)__cvta_generic_to_shared(p);
}

#define MMA_TF32(d, a0, a1, a2, a3, b0, b1)                                   \
    asm volatile("mma.sync.aligned.m16n8k8.row.col.f32.tf32.tf32.f32 "       \
                 "{%0,%1,%2,%3}, {%4,%5,%6,%7}, {%8,%9}, {%0,%1,%2,%3};"     \
                 : "+f"(d[0]), "+f"(d[1]), "+f"(d[2]), "+f"(d[3])            \
                 : "r"(a0), "r"(a1), "r"(a2), "r"(a3), "r"(b0), "r"(b1))

#define LDSM4(r, addr)                                                        \
    asm volatile("ldmatrix.sync.aligned.m8n8.x4.shared.b16 {%0,%1,%2,%3}, [%4];" \
                 : "=r"(r[0]), "=r"(r[1]), "=r"(r[2]), "=r"(r[3]) : "r"(addr))

// ============================================================================
// BIG tf32 GEMM NT: 128x128 tile, 256 threads, 8 warps (2x4), 64x32 warp
// tiles. Dynamic smem (80KB), double-buffered, ldmatrix fragments.
// ============================================================================
#define BUFW (128 * SSTR)   // words per buffer stage

template<bool P3>
__device__ __forceinline__ void tf32_big_body(
    u32t* As, u32t* Bs, u32t* Asl, u32t* Bsl,
    const float* __restrict__ A, const float* __restrict__ B,
    float* __restrict__ C, int N, int K, const float* __restrict__ bias,
    int tileX, int tileY)
{
    const int tid  = threadIdx.x;
    const int warp = tid >> 5;
    const int lane = tid & 31;
    const int g    = lane >> 2;
    const int tg   = lane & 3;
    const int wm   = (warp >> 2) * 64;   // 2 warp-rows of 64
    const int wn   = (warp & 3) * 32;    // 4 warp-cols of 32
    const int brow = tileY * 128;
    const int bcol = tileX * 128;

    const int lrow8   = lane & 7;
    const int aRowOff = lrow8 + ((lane >> 3) & 1) * 8;
    const int aKsel   = (lane >> 4) * 4;
    const int bRow    = wn + (lane >> 3) * 8 + lrow8;

    float4 pa[2], pb[2];

    auto loadA = [&](int k0) {
#pragma unroll
        for (int i = 0; i < 2; i++) {
            int slot = tid + i * 256;
            int row = slot >> 2, kq = slot & 3;
            pa[i] = *(const float4*)(A + (size_t)(brow + row) * K + k0 + kq * 4);
        }
    };
    auto loadB = [&](int k0) {
#pragma unroll
        for (int i = 0; i < 2; i++) {
            int slot = tid + i * 256;
            int row = slot >> 2, kq = slot & 3;
            pb[i] = *(const float4*)(B + (size_t)(bcol + row) * K + k0 + kq * 4);
        }
    };
    auto split_store = [&](u32t* hi, u32t* lo, int buf, float4* p) {
#pragma unroll
        for (int i = 0; i < 2; i++) {
            int slot = tid + i * 256;
            int row = slot >> 2, kq = slot & 3;
            float v[4] = {p[i].x, p[i].y, p[i].z, p[i].w};
            uint4 qh_, ql_;
            u32t* qhp = (u32t*)&qh_;
            u32t* qlp = (u32t*)&ql_;
#pragma unroll
            for (int c = 0; c < 4; c++) {
                u32t h = cvt_tf32(v[c]);
                qhp[c] = h;
                if (P3) qlp[c] = cvt_tf32(v[c] - __uint_as_float(h));
            }
            *(uint4*)&hi[buf * BUFW + row * SSTR + kq * 4] = qh_;
            if (P3) *(uint4*)&lo[buf * BUFW + row * SSTR + kq * 4] = ql_;
        }
    };

    float acc[4][4][4];
#pragma unroll
    for (int mi = 0; mi < 4; mi++)
#pragma unroll
        for (int ni = 0; ni < 4; ni++)
#pragma unroll
            for (int r = 0; r < 4; r++) acc[mi][ni][r] = 0.f;

    const int ntiles = K / TBK;
    loadA(0); loadB(0);
    split_store(As, Asl, 0, pa);
    split_store(Bs, Bsl, 0, pb);
    __syncthreads();

    for (int t = 0; t < ntiles; t++) {
        const int cur = t & 1;
        const bool more = (t + 1 < ntiles);
        if (more) { loadA((t + 1) * TBK); loadB((t + 1) * TBK); }

#pragma unroll
        for (int ks = 0; ks < 2; ks++) {
            const int kb = ks * 8;
            u32t a[4][4], bb0[4], bb1[4];
            u32t al[4][4], bl0[4], bl1[4];
#pragma unroll
            for (int mi = 0; mi < 4; mi++) {
                u32t addr = smem_u32(&As[cur * BUFW + (wm + mi * 16 + aRowOff) * SSTR + kb + aKsel]);
                LDSM4(a[mi], addr);
                if (P3) {
                    u32t addrl = smem_u32(&Asl[cur * BUFW + (wm + mi * 16 + aRowOff) * SSTR + kb + aKsel]);
                    LDSM4(al[mi], addrl);
                }
            }
            {
                LDSM4(bb0, smem_u32(&Bs[cur * BUFW + bRow * SSTR + kb]));
                LDSM4(bb1, smem_u32(&Bs[cur * BUFW + bRow * SSTR + kb + 4]));
                if (P3) {
                    LDSM4(bl0, smem_u32(&Bsl[cur * BUFW + bRow * SSTR + kb]));
                    LDSM4(bl1, smem_u32(&Bsl[cur * BUFW + bRow * SSTR + kb + 4]));
                }
            }
#pragma unroll
            for (int mi = 0; mi < 4; mi++)
#pragma unroll
                for (int ni = 0; ni < 4; ni++) {
                    if (P3) {
                        MMA_TF32(acc[mi][ni], a[mi][0], a[mi][1], a[mi][2], a[mi][3],
                                 bl0[ni], bl1[ni]);                        // hi*lo
                        MMA_TF32(acc[mi][ni], al[mi][0], al[mi][1], al[mi][2], al[mi][3],
                                 bb0[ni], bb1[ni]);                        // lo*hi
                    }
                    MMA_TF32(acc[mi][ni], a[mi][0], a[mi][1], a[mi][2], a[mi][3],
                             bb0[ni], bb1[ni]);                            // hi*hi
                }
        }
        if (more) {
            split_store(As, Asl, cur ^ 1, pa);
            split_store(Bs, Bsl, cur ^ 1, pb);
        }
        __syncthreads();
    }

#pragma unroll
    for (int mi = 0; mi < 4; mi++) {
        const int r0 = brow + wm + mi * 16 + g;
#pragma unroll
        for (int ni = 0; ni < 4; ni++) {
            const int c = bcol + wn + ni * 8 + 2 * tg;
            float b0 = 0.f, b1 = 0.f;
            if (bias) { b0 = bias[c]; b1 = bias[c + 1]; }
            float2 o0 = make_float2(acc[mi][ni][0] + b0, acc[mi][ni][1] + b1);
            float2 o1 = make_float2(acc[mi][ni][2] + b0, acc[mi][ni][3] + b1);
            *(float2*)(C + (size_t)r0 * N + c)       = o0;
            *(float2*)(C + (size_t)(r0 + 8) * N + c) = o1;
        }
    }
}

__global__ void __launch_bounds__(256)
gemm8t(GT t0, GT t1, GT t2, GT t3, int e0, int e1, int e2)
{
    extern __shared__ u32t dsm[];
    u32t* As  = dsm;
    u32t* Bs  = dsm + 2 * BUFW;
    u32t* Asl = dsm + 4 * BUFW;
    u32t* Bsl = dsm + 6 * BUFW;
    const int bx = blockIdx.x;
    GT t; int local;
    if (bx < e0)      { t = t0; local = bx; }
    else if (bx < e1) { t = t1; local = bx - e0; }
    else if (bx < e2) { t = t2; local = bx - e1; }
    else              { t = t3; local = bx - e2; }
    const int tX = local % t.tilesX;
    const int tY = local / t.tilesX;
    if (t.prec3)
        tf32_big_body<true>(As, Bs, Asl, Bsl, t.A, t.B, t.C, t.N, t.K, t.bias, tX, tY);
    else
        tf32_big_body<false>(As, Bs, Asl, Bsl, t.A, t.B, t.C, t.N, t.K, t.bias, tX, tY);
}

// ============================================================================
// SMALL tf32 GEMM NT: 64x64 tile, 128 threads (2x2 of 32x32) — for N%128!=0
// tasks and tiny precomputes. (Proven R9 kernel.)
// ============================================================================
template<bool P3>
__device__ __forceinline__ void tf32_body(
    u32t (*As)[64][SSTR], u32t (*Bs)[64][SSTR],
    u32t (*Asl)[64][SSTR], u32t (*Bsl)[64][SSTR],
    const float* __restrict__ A, const float* __restrict__ B,
    float* __restrict__ C, int N, int K, const float* __restrict__ bias,
    int tileX, int tileY)
{
    const int tid  = threadIdx.x;
    const int warp = tid >> 5;
    const int lane = tid & 31;
    const int g    = lane >> 2;
    const int tg   = lane & 3;
    const int wm   = (warp >> 1) * 32;
    const int wn   = (warp & 1) * 32;
    const int brow = tileY * 64;
    const int bcol = tileX * 64;

    const int lrow8   = lane & 7;
    const int aRowOff = lrow8 + ((lane >> 3) & 1) * 8;
    const int aKsel   = (lane >> 4) * 4;
    const int bRow    = wn + (lane >> 3) * 8 + lrow8;

    float4 pa[2], pb[2];

    auto loadA = [&](int k0) {
#pragma unroll
        for (int i = 0; i < 2; i++) {
            int slot = tid + i * 128;
            int row = slot >> 2, kq = slot & 3;
            pa[i] = *(const float4*)(A + (size_t)(brow + row) * K + k0 + kq * 4);
        }
    };
    auto loadB = [&](int k0) {
#pragma unroll
        for (int i = 0; i < 2; i++) {
            int slot = tid + i * 128;
            int row = slot >> 2, kq = slot & 3;
            pb[i] = *(const float4*)(B + (size_t)(bcol + row) * K + k0 + kq * 4);
        }
    };
    auto split_store = [&](u32t (*hi)[64][SSTR], u32t (*lo)[64][SSTR],
                           int buf, float4* p) {
#pragma unroll
        for (int i = 0; i < 2; i++) {
            int slot = tid + i * 128;
            int row = slot >> 2, kq = slot & 3;
            float v[4] = {p[i].x, p[i].y, p[i].z, p[i].w};
            uint4 qh_, ql_;
            u32t* qhp = (u32t*)&qh_;
            u32t* qlp = (u32t*)&ql_;
#pragma unroll
            for (int c = 0; c < 4; c++) {
                u32t h = cvt_tf32(v[c]);
                qhp[c] = h;
                if (P3) qlp[c] = cvt_tf32(v[c] - __uint_as_float(h));
            }
            *(uint4*)&hi[buf][row][kq * 4] = qh_;
            if (P3) *(uint4*)&lo[buf][row][kq * 4] = ql_;
        }
    };

    float acc[2][4][4];
#pragma unroll
    for (int mi = 0; mi < 2; mi++)
#pragma unroll
        for (int ni = 0; ni < 4; ni++)
#pragma unroll
            for (int r = 0; r < 4; r++) acc[mi][ni][r] = 0.f;

    const int ntiles = K / TBK;
    loadA(0); loadB(0);
    split_store(As, Asl, 0, pa);
    split_store(Bs, Bsl, 0, pb);
    __syncthreads();

    for (int t = 0; t < ntiles; t++) {
        const int cur = t & 1;
        const bool more = (t + 1 < ntiles);
        if (more) { loadA((t + 1) * TBK); loadB((t + 1) * TBK); }

#pragma unroll
        for (int ks = 0; ks < 2; ks++) {
            const int kb = ks * 8;
            u32t a[2][4], bb0[4], bb1[4];
            u32t al[2][4], bl0[4], bl1[4];
#pragma unroll
            for (int mi = 0; mi < 2; mi++) {
                LDSM4(a[mi], smem_u32(&As[cur][wm + mi * 16 + aRowOff][kb + aKsel]));
                if (P3)
                    LDSM4(al[mi], smem_u32(&Asl[cur][wm + mi * 16 + aRowOff][kb + aKsel]));
            }
            LDSM4(bb0, smem_u32(&Bs[cur][bRow][kb]));
            LDSM4(bb1, smem_u32(&Bs[cur][bRow][kb + 4]));
            if (P3) {
                LDSM4(bl0, smem_u32(&Bsl[cur][bRow][kb]));
                LDSM4(bl1, smem_u32(&Bsl[cur][bRow][kb + 4]));
            }
#pragma unroll
            for (int mi = 0; mi < 2; mi++)
#pragma unroll
                for (int ni = 0; ni < 4; ni++) {
                    if (P3) {
                        MMA_TF32(acc[mi][ni], a[mi][0], a[mi][1], a[mi][2], a[mi][3],
                                 bl0[ni], bl1[ni]);
                        MMA_TF32(acc[mi][ni], al[mi][0], al[mi][1], al[mi][2], al[mi][3],
                                 bb0[ni], bb1[ni]);
                    }
                    MMA_TF32(acc[mi][ni], a[mi][0], a[mi][1], a[mi][2], a[mi][3],
                             bb0[ni], bb1[ni]);
                }
        }
        if (more) {
            split_store(As, Asl, cur ^ 1, pa);
            split_store(Bs, Bsl, cur ^ 1, pb);
        }
        __syncthreads();
    }

#pragma unroll
    for (int mi = 0; mi < 2; mi++) {
        const int r0 = brow + wm + mi * 16 + g;
#pragma unroll
        for (int ni = 0; ni < 4; ni++) {
            const int c = bcol + wn + ni * 8 + 2 * tg;
            float b0 = 0.f, b1 = 0.f;
            if (bias) { b0 = bias[c]; b1 = bias[c + 1]; }
            float2 o0 = make_float2(acc[mi][ni][0] + b0, acc[mi][ni][1] + b1);
            float2 o1 = make_float2(acc[mi][ni][2] + b0, acc[mi][ni][3] + b1);
            *(float2*)(C + (size_t)r0 * N + c)       = o0;
            *(float2*)(C + (size_t)(r0 + 8) * N + c) = o1;
        }
    }
}

__global__ void __launch_bounds__(128)
gemm4t(GT t0, GT t1, GT t2, GT t3, int e0, int e1, int e2)
{
    __shared__ u32t sm[4][2][64][SSTR];
    const int bx = blockIdx.x;
    GT t; int local;
    if (bx < e0)      { t = t0; local = bx; }
    else if (bx < e1) { t = t1; local = bx - e0; }
    else if (bx < e2) { t = t2; local = bx - e1; }
    else              { t = t3; local = bx - e2; }
    const int tX = local % t.tilesX;
    const int tY = local / t.tilesX;
    if (t.prec3)
        tf32_body<true>(sm[0], sm[1], sm[2], sm[3], t.A, t.B, t.C, t.N, t.K, t.bias, tX, tY);
    else
        tf32_body<false>(sm[0], sm[1], sm[2], sm[3], t.A, t.B, t.C, t.N, t.K, t.bias, tX, tY);
}

// ---------------- transpose Wqp [512,320] -> WqpT [320,512] -----------------
__global__ __launch_bounds__(256)
void transpose_kernel(const float* __restrict__ src, float* __restrict__ dst)
{
    __shared__ float tile[32][33];
    const int bx = blockIdx.x;
    const int by = blockIdx.y;
    const int txx = threadIdx.x;
    const int tyy = threadIdx.y;
    const int x  = bx * 32 + txx;
    const int y0 = by * 32 + tyy;
#pragma unroll
    for (int i = 0; i < 32; i += 8)
        tile[tyy + i][txx] = src[(size_t)(y0 + i) * QDIM + x];
    __syncthreads();
    const int dx  = by * 32 + txx;
    const int dy0 = bx * 32 + tyy;
#pragma unroll
    for (int i = 0; i < 32; i += 8)
        dst[(size_t)(dy0 + i) * DDIM + dx] = tile[txx][tyy + i];
}

// ---------------- L2 normalize memory slots (keys & values) ----------------
__global__ __launch_bounds__(256)
void l2norm_kernel(const float* __restrict__ keys, const float* __restrict__ vals)
{
    __shared__ float sbuf[8];
    const int row = blockIdx.x;
    const float* src = (blockIdx.y == 0) ? keys : vals;
    float* dst = (blockIdx.y == 0) ? g_keysN : g_valsN;
    const int t = threadIdx.x;

    float2 v = *(const float2*)(src + (size_t)row * DDIM + t * 2);
    float ss = v.x * v.x + v.y * v.y;
#pragma unroll
    for (int off = 16; off; off >>= 1) ss += __shfl_xor_sync(0xffffffffu, ss, off);
    if ((t & 31) == 0) sbuf[t >> 5] = ss;
    __syncthreads();
    float tot = 0.f;
#pragma unroll
    for (int w = 0; w < 8; w++) tot += sbuf[w];
    float inv = 1.0f / sqrtf(tot + 1e-12f);
    float2 o = make_float2(v.x * inv, v.y * inv);
    *(float2*)(dst + (size_t)row * DDIM + t * 2) = o;
}

// ============================================================================
// Fused top-32 (exact 4-pass radix select) + gathered multi-head attention.
// ============================================================================
__device__ __forceinline__ u32t f2ord(float f) {
    u32t b = __float_as_uint(f);
    return (b & 0x80000000u) ? ~b : (b | 0x80000000u);
}

__global__ __launch_bounds__(256)
void topk_attn_kernel(const float* __restrict__ scores,
                      const float* __restrict__ qh,
                      float* __restrict__ ctx)
{
    __shared__ u32t  s_hist[256];
    __shared__ u32t  s_suf[257];
    __shared__ int   s_idx[KSEL];
    __shared__ int   s_tie[KSEL];
    __shared__ int   s_cnt[2];
    __shared__ int   s_T;
    __shared__ float s_q[DDIM];
    __shared__ float s_dot[NHEAD][KSEL];

    const int row = blockIdx.x;
    const int t = threadIdx.x;
    const int lane = t & 31;
    const int wrp = t >> 5;

    u32t u[4];
#pragma unroll
    for (int j = 0; j < 4; j++)
        u[j] = f2ord(scores[(size_t)row * SSLOTS + t + j * 256]);
    s_q[t]       = qh[(size_t)row * DDIM + t];
    s_q[t + 256] = qh[(size_t)row * DDIM + t + 256];
    if (t < 2) s_cnt[t] = 0;

    u32t prefix = 0;
    int  need   = KSEL;

#pragma unroll
    for (int b = 3; b >= 0; b--) {
        const int sh = b * 8;
        s_hist[t] = 0;
        __syncthreads();
#pragma unroll
        for (int j = 0; j < 4; j++) {
            bool in = (b == 3) || ((u[j] >> (sh + 8)) == prefix);
            if (in) atomicAdd(&s_hist[(u[j] >> sh) & 255u], 1u);
        }
        __syncthreads();
        {
            u32t v = s_hist[t];
#pragma unroll
            for (int off = 1; off < 32; off <<= 1) {
                u32t o = __shfl_down_sync(0xffffffffu, v, off);
                if (lane + off < 32) v += o;
            }
            __shared__ u32t wsum[8];
            if (lane == 0) wsum[wrp] = v;
            __syncthreads();
            u32t woff = 0;
#pragma unroll
            for (int w = 0; w < 8; w++) woff += (w > wrp) ? wsum[w] : 0u;
            s_suf[t] = v + woff;
            if (t == 0) s_suf[256] = 0;
        }
        __syncthreads();
        if (s_suf[t] >= (u32t)need && s_suf[t + 1] < (u32t)need) s_T = t;
        __syncthreads();
        const int T = s_T;
        need -= (int)s_suf[T + 1];
        prefix = (prefix << 8) | (u32t)T;
        __syncthreads();
    }
    const u32t V = prefix;

#pragma unroll
    for (int j = 0; j < 4; j++) {
        if (u[j] > V) {
            int p = atomicAdd(&s_cnt[0], 1);
            s_idx[p] = t + j * 256;
        } else if (u[j] == V) {
            int p = atomicAdd(&s_cnt[1], 1);
            if (p < KSEL) s_tie[p] = t + j * 256;
        }
    }
    __syncthreads();
    if (t == 0) {
        int nt = min(s_cnt[1], KSEL);
        int base = s_cnt[0];
        for (int r = 0; r < need; r++) {
            int best = 1 << 30, bj = -1;
            for (int j = 0; j < nt; j++)
                if (s_tie[j] < best) { best = s_tie[j]; bj = j; }
            s_idx[base + r] = best;
            s_tie[bj] = 1 << 30;
        }
    }
    __syncthreads();

    // ---- attention: warp = head; coalesced cooperative dots ----
    const int h  = wrp;
    const int g  = lane >> 4;
    const int gl = lane & 15;

    const int myidx = s_idx[lane];

    float4 qv = *(const float4*)&s_q[h * DHEAD + gl * 4];

#pragma unroll
    for (int i = 0; i < 16; i++) {
        const int slot = i * 2 + g;
        const int rowi = __shfl_sync(0xffffffffu, myidx, slot);
        float4 kv = *(const float4*)(g_Kp + (size_t)rowi * DDIM + h * DHEAD + gl * 4);
        float p = qv.x * kv.x + qv.y * kv.y + qv.z * kv.z + qv.w * kv.w;
        p += __shfl_xor_sync(0xffffffffu, p, 8);
        p += __shfl_xor_sync(0xffffffffu, p, 4);
        p += __shfl_xor_sync(0xffffffffu, p, 2);
        p += __shfl_xor_sync(0xffffffffu, p, 1);
        if (gl == 0) s_dot[h][slot] = p;
    }
    __syncwarp();

    float dot = s_dot[h][lane] * 0.125f;
    float m = dot;
#pragma unroll
    for (int off = 16; off; off >>= 1) m = fmaxf(m, __shfl_xor_sync(0xffffffffu, m, off));
    float e = expf(dot - m);
    float s = e;
#pragma unroll
    for (int off = 16; off; off >>= 1) s += __shfl_xor_sync(0xffffffffu, s, off);
    const float myw = e / s;

    {
        const int d2 = t * 2;
        float2 acc = make_float2(0.f, 0.f);
#pragma unroll 8
        for (int kk = 0; kk < KSEL; kk++) {
            const float wv = __shfl_sync(0xffffffffu, myw, kk);
            const int rk = __shfl_sync(0xffffffffu, myidx, kk);
            float2 v = *(const float2*)(g_Vp + (size_t)rk * DDIM + d2);
            acc.x = fmaf(wv, v.x, acc.x);
            acc.y = fmaf(wv, v.y, acc.y);
        }
        *(float2*)(ctx + (size_t)row * DDIM + d2) = acc;
    }
}

// ---------------- LayerNorm over D=512 -------------------------------------
__global__ __launch_bounds__(256)
void ln_kernel(const float* __restrict__ x, const float* __restrict__ g,
               const float* __restrict__ b, float* __restrict__ y)
{
    __shared__ float sbuf[8];
    __shared__ float sbuf2[8];
    const int row = blockIdx.x;
    const int t = threadIdx.x;

    float2 v = *(const float2*)(x + (size_t)row * DDIM + t * 2);
    float s = v.x + v.y;
#pragma unroll
    for (int off = 16; off; off >>= 1) s += __shfl_xor_sync(0xffffffffu, s, off);
    if ((t & 31) == 0) sbuf[t >> 5] = s;
    __syncthreads();
    float tot = 0.f;
#pragma unroll
    for (int w = 0; w < 8; w++) tot += sbuf[w];
    float mu = tot * (1.0f / DDIM);

    float dx = v.x - mu, dy = v.y - mu;
    float ss = dx * dx + dy * dy;
#pragma unroll
    for (int off = 16; off; off >>= 1) ss += __shfl_xor_sync(0xffffffffu, ss, off);
    if ((t & 31) == 0) sbuf2[t >> 5] = ss;
    __syncthreads();
    float vs = 0.f;
#pragma unroll
    for (int w = 0; w < 8; w++) vs += sbuf2[w];
    float rstd = 1.0f / sqrtf(vs * (1.0f / DDIM) + 1e-5f);

    float2 o;
    o.x = dx * rstd * g[t * 2 + 0] + b[t * 2 + 0];
    o.y = dy * rstd * g[t * 2 + 1] + b[t * 2 + 1];
    *(float2*)(y + (size_t)row * DDIM + t * 2) = o;
}

// ---------------- launch ----------------------------------------------------
extern "C" void kernel_launch(void* const* d_in, const int* in_sizes, int n_in,
                              void* d_out, int out_size)
{
    const float* query = (const float*)d_in[0];
    const float* Wqp   = (const float*)d_in[1];
    const float* mkeys = (const float*)d_in[2];
    const float* mvals = (const float*)d_in[3];
    const float* Wq    = (const float*)d_in[4];
    const float* Wk    = (const float*)d_in[5];
    const float* Wv    = (const float*)d_in[6];
    const float* Wo    = (const float*)d_in[7];
    const float* ln_g  = (const float*)d_in[8];
    const float* ln_b  = (const float*)d_in[9];
    const float* Wout  = (const float*)d_in[10];
    const float* bout  = (const float*)d_in[11];
    float* out = (float*)d_out;

    float *keysN, *valsN, *Kp, *Vp, *qh, *scores, *ctx, *ctxo, *normed;
    float *WqpT, *Wqq, *M;
    cudaGetSymbolAddress((void**)&keysN,  g_keysN);
    cudaGetSymbolAddress((void**)&valsN,  g_valsN);
    cudaGetSymbolAddress((void**)&Kp,     g_Kp);
    cudaGetSymbolAddress((void**)&Vp,     g_Vp);
    cudaGetSymbolAddress((void**)&qh,     g_qh);
    cudaGetSymbolAddress((void**)&scores, g_scores);
    cudaGetSymbolAddress((void**)&ctx,    g_ctx);
    cudaGetSymbolAddress((void**)&ctxo,   g_ctxo);
    cudaGetSymbolAddress((void**)&normed, g_normed);
    cudaGetSymbolAddress((void**)&WqpT,   g_WqpT);
    cudaGetSymbolAddress((void**)&Wqq,    g_Wqq);
    cudaGetSymbolAddress((void**)&M,      g_M);

    static int smem_set = 0;
    const int BIG_SMEM = 8 * BUFW * 4;   // 81920 bytes
    if (!smem_set) {
        cudaFuncSetAttribute(gemm8t, cudaFuncAttributeMaxDynamicSharedMemorySize, BIG_SMEM);
        smem_set = 1;
    }

    // 1) normalize slot tables; transpose Wqp
    l2norm_kernel<<<dim3(SSLOTS, 2), 256>>>(mkeys, mvals);
    transpose_kernel<<<dim3(QDIM / 32, DDIM / 32), dim3(32, 8)>>>(Wqp, WqpT);

    // 2) small precomputes: M = keysN @ WqpT^T [1024,320] 3xTF32; Wqq tf32
    {
        GT tm   = {keysN, WqpT, M,   QDIM, DDIM, nullptr, QDIM / 64, 1};
        GT twqq = {Wq,    WqpT, Wqq, QDIM, DDIM, nullptr, QDIM / 64, 0};
        GT dmy  = twqq;
        gemm4t<<<80 + 40, 128>>>(tm, twqq, dmy, dmy, 80, 120, 120);
    }

    // 3) BIG launch (448 blocks of 128x128 tiles):
    //    scores = query @ M^T  [4096,1024] K=320 3xTF32 (256 tiles)
    //    qh     = query @ Wqq^T [4096,512] K=320 tf32   (128)
    //    Kp     = keysN @ Wk^T  [1024,512] K=512 tf32   (32)
    //    Vp     = valsN @ Wv^T  [1024,512] K=512 tf32   (32)
    {
        GT tsc = {query, M,   scores, SSLOTS, QDIM, nullptr, SSLOTS / 128, 1};
        GT tqh = {query, Wqq, qh,     DDIM,   QDIM, nullptr, DDIM / 128,   0};
        GT tkp = {keysN, Wk,  Kp,     DDIM,   DDIM, nullptr, DDIM / 128,   0};
        GT tvp = {valsN, Wv,  Vp,     DDIM,   DDIM, nullptr, DDIM / 128,   0};
        gemm8t<<<256 + 128 + 32 + 32, 256, BIG_SMEM>>>(tsc, tqh, tkp, tvp, 256, 384, 416);
    }

    // 4) fused radix-select top-32 + attention -> ctx [4096,512]
    topk_attn_kernel<<<TOKS, 256>>>(scores, qh, ctx);

    // 5) ctxo = ctx @ Wo^T [4096,512] (128 tiles of 128x128)
    {
        GT two = {ctx, Wo, ctxo, DDIM, DDIM, nullptr, DDIM / 128, 0};
        gemm8t<<<128, 256, BIG_SMEM>>>(two, two, two, two, 128, 128, 128);
    }

    // 6) LayerNorm
    ln_kernel<<<TOKS, 256>>>(ctxo, ln_g, ln_b, normed);

    // 7) out = normed @ Wout^T + bout [4096,320] (320 tiles of 64x64)
    {
        GT tout = {normed, Wout, out, QDIM, DDIM, bout, QDIM / 64, 0};
        gemm4t<<<320, 128>>>(tout, tout, tout, tout, 320, 320, 320);
    }
}